// round 8
// baseline (speedup 1.0000x reference)
#include <cuda_runtime.h>
#include <cuda_bf16.h>
#include <cstdint>

#define MARGIN 0.5f
#define POS_W 1.0f
#define NEG_W 1.0f

#define BLOCKS_PER_BATCH 2
#define R_THREADS 256
#define STAGES 4
#define CHUNK_F4 512                      // float4 per chunk = 8 KB
#define CHUNK_BYTES (CHUNK_F4 * 16)
#define MAX_PARTIALS 8192
#define MAX_B 1024

// Scratch (allocations forbidden; __device__ globals).
__device__ float g_partial[MAX_PARTIALS];
__device__ unsigned int g_arrival = 0;   // last block resets to 0 each call

// ---- mbarrier / bulk-async helpers ----
__device__ __forceinline__ uint32_t smem_u32(const void* p) {
    return (uint32_t)__cvta_generic_to_shared(p);
}
__device__ __forceinline__ void mbar_init(uint32_t a, uint32_t cnt) {
    asm volatile("mbarrier.init.shared.b64 [%0], %1;" :: "r"(a), "r"(cnt) : "memory");
}
__device__ __forceinline__ void mbar_expect_tx(uint32_t a, uint32_t bytes) {
    asm volatile("mbarrier.arrive.expect_tx.shared.b64 _, [%0], %1;"
                 :: "r"(a), "r"(bytes) : "memory");
}
__device__ __forceinline__ void bulk_g2s(uint32_t dst, const void* src,
                                         uint32_t bytes, uint32_t bar) {
    asm volatile("cp.async.bulk.shared::cta.global.mbarrier::complete_tx::bytes "
                 "[%0], [%1], %2, [%3];"
                 :: "r"(dst), "l"(src), "r"(bytes), "r"(bar) : "memory");
}
__device__ __forceinline__ void mbar_wait(uint32_t a, uint32_t parity) {
    asm volatile(
        "{\n\t.reg .pred P;\n\t"
        "W_%=:\n\t"
        "mbarrier.try_wait.parity.acquire.cta.shared::cta.b64 P, [%0], %1, 10000000;\n\t"
        "@!P bra W_%=;\n\t}"
        :: "r"(a), "r"(parity) : "memory");
}

__global__ __launch_bounds__(R_THREADS) void fused_loss_kernel(
    const float* __restrict__ graph,
    const int* __restrict__ labels,
    float* __restrict__ out,
    int B, int ne_per_batch) {

    __shared__ __align__(128) float4 buf[STAGES][CHUNK_F4];
    __shared__ __align__(8) uint64_t mbar[STAGES];

    const int tid = threadIdx.x;
    const int vec_per_batch = ne_per_batch >> 2;
    const int vec_per_block = vec_per_batch / BLOCKS_PER_BATCH;     // 32768
    const int nchunks = vec_per_block / CHUNK_F4;                   // 64

    const char* gsrc = (const char*)graph +
                       (size_t)blockIdx.x * (size_t)vec_per_block * 16;

    uint32_t mb[STAGES];
    #pragma unroll
    for (int s = 0; s < STAGES; ++s) mb[s] = smem_u32(&mbar[s]);

    if (tid == 0) {
        #pragma unroll
        for (int s = 0; s < STAGES; ++s) mbar_init(mb[s], 1);
    }
    __syncthreads();

    // Prologue: issue up to STAGES chunks ahead.
    if (tid == 0) {
        #pragma unroll
        for (int s = 0; s < STAGES; ++s) {
            if (s < nchunks) {
                mbar_expect_tx(mb[s], CHUNK_BYTES);
                bulk_g2s(smem_u32(&buf[s][0]), gsrc + (size_t)s * CHUNK_BYTES,
                         CHUNK_BYTES, mb[s]);
            }
        }
    }

    float acc0 = 0.0f, acc1 = 0.0f;
    uint32_t phase = 0;   // bit s = current parity of stage s
    for (int c = 0; c < nchunks; ++c) {
        const int j = c & (STAGES - 1);
        mbar_wait(mb[j], (phase >> j) & 1u);
        phase ^= (1u << j);

        float4 v0 = buf[j][tid];
        float4 v1 = buf[j][tid + R_THREADS];
        acc0 += (v0.x + v0.y) + (v0.z + v0.w);
        acc1 += (v1.x + v1.y) + (v1.z + v1.w);

        __syncthreads();   // all reads of buf[j] done before refill
        if (tid == 0 && c + STAGES < nchunks) {
            mbar_expect_tx(mb[j], CHUNK_BYTES);
            bulk_g2s(smem_u32(&buf[j][0]),
                     gsrc + (size_t)(c + STAGES) * CHUNK_BYTES,
                     CHUNK_BYTES, mb[j]);
        }
    }
    float acc = acc0 + acc1;

    // block reduce
    #pragma unroll
    for (int off = 16; off > 0; off >>= 1)
        acc += __shfl_xor_sync(0xFFFFFFFFu, acc, off);

    __shared__ float warp_sums[R_THREADS / 32];
    const int lane = tid & 31, wid = tid >> 5;
    if (lane == 0) warp_sums[wid] = acc;
    __syncthreads();

    __shared__ bool is_last;
    if (wid == 0) {
        float s = (lane < R_THREADS / 32) ? warp_sums[lane] : 0.0f;
        #pragma unroll
        for (int off = 4; off > 0; off >>= 1)
            s += __shfl_xor_sync(0xFFFFFFFFu, s, off);
        if (lane == 0) {
            g_partial[blockIdx.x] = s;
            __threadfence();
            unsigned int prev = atomicAdd(&g_arrival, 1u);
            is_last = (prev == gridDim.x - 1);
        }
    }
    __syncthreads();

    if (!is_last) return;

    // ---- tail: last block computes pooled sims + pair loss ----
    if (tid == 0) g_arrival = 0;   // reset for next graph replay

    // Reuse stage buffers for the tail arrays (buffers are dead here).
    float* gs = reinterpret_cast<float*>(&buf[0][0]);
    int* lab = reinterpret_cast<int*>(&buf[1][0]);
    const float inv_ne = 1.0f / (float)ne_per_batch;

    for (int t = tid; t < B; t += R_THREADS) {
        float s = 0.0f;
        #pragma unroll
        for (int c = 0; c < BLOCKS_PER_BATCH; ++c)
            s += g_partial[t * BLOCKS_PER_BATCH + c];
        gs[t] = s * inv_ne;
        lab[t] = labels[t];
    }
    __syncthreads();

    float pacc = 0.0f;
    for (int t = tid; t < B; t += R_THREADS) {
        const float gi = gs[t];
        const int li = lab[t];
        for (int j = t + 1; j < B; ++j) {
            const float sim = gi * gs[j];
            const float pos = fmaxf(MARGIN - sim, 0.0f);
            const float neg = fmaxf(sim - (1.0f - MARGIN), 0.0f);
            pacc += (li == lab[j]) ? (POS_W * pos) : (NEG_W * neg);
        }
    }

    #pragma unroll
    for (int off = 16; off > 0; off >>= 1)
        pacc += __shfl_xor_sync(0xFFFFFFFFu, pacc, off);

    __shared__ float pw[R_THREADS / 32];
    if (lane == 0) pw[wid] = pacc;
    __syncthreads();

    if (wid == 0) {
        float s = (lane < R_THREADS / 32) ? pw[lane] : 0.0f;
        #pragma unroll
        for (int off = 4; off > 0; off >>= 1)
            s += __shfl_xor_sync(0xFFFFFFFFu, s, off);
        if (lane == 0) {
            const float num_pairs = 0.5f * (float)B * (float)(B - 1);
            out[0] = s / num_pairs;
        }
    }
}

extern "C" void kernel_launch(void* const* d_in, const int* in_sizes, int n_in,
                              void* d_out, int out_size) {
    const float* graph = (const float*)d_in[0];
    const int* labels = (const int*)d_in[1];
    float* out = (float*)d_out;

    const int total = in_sizes[0];   // B * N * N
    const int B = in_sizes[1];       // 256
    const int ne = total / B;        // N*N = 262144

    fused_loss_kernel<<<B * BLOCKS_PER_BATCH, R_THREADS>>>(graph, labels, out, B, ne);
}